// round 3
// baseline (speedup 1.0000x reference)
#include <cuda_runtime.h>
#include <cstdint>

#define SDIM 1024
#define BHN  64
#define KT   32
#define PAD  4

// 256 MB scratch for logits / attention weights (device global: allocation-free).
__device__ __align__(16) float g_attn[(size_t)BHN * SDIM * SDIM];

__device__ __forceinline__ uint32_t f2tf(float x) {
    uint32_t r;
    asm("cvt.rna.tf32.f32 %0, %1;" : "=r"(r) : "f"(x));
    return r;
}

__device__ __forceinline__ void mma_tf32(float c[4], const uint32_t a[4], const uint32_t b[2]) {
    asm volatile(
        "mma.sync.aligned.m16n8k8.row.col.f32.tf32.tf32.f32 "
        "{%0,%1,%2,%3}, {%4,%5,%6,%7}, {%8,%9}, {%0,%1,%2,%3};"
        : "+f"(c[0]), "+f"(c[1]), "+f"(c[2]), "+f"(c[3])
        : "r"(a[0]), "r"(a[1]), "r"(a[2]), "r"(a[3]), "r"(b[0]), "r"(b[1]));
}

// C-tile = 128x128, 8 warps (2 x 4), warp tile 64x32, mma m16n8k8 tf32.
// mode 1: out = (acc + AddM) * scale + Mask   (QK pass -> g_attn)
// mode 0: out = acc                           (attn @ P -> d_out)
__global__ __launch_bounds__(256) void gemm_kernel(
    const float* __restrict__ Ag, const float* __restrict__ Bg,
    const float* __restrict__ AddM, const float* __restrict__ Mask,
    float* __restrict__ Out, int fuse_epi)
{
    __shared__ uint32_t As[KT][128 + PAD];  // [k][m]
    __shared__ uint32_t Bs[KT][128 + PAD];  // [k][n]

    const int bm = blockIdx.x, bn = blockIdx.y, bh = blockIdx.z;
    const int tid  = threadIdx.x;
    const int warp = tid >> 5, lane = tid & 31;
    const int wm = warp >> 2, wn = warp & 3;   // 2 x 4 warp grid
    const int lr = lane >> 2, lc = lane & 3;

    const size_t mat = (size_t)bh * SDIM * SDIM;
    const float* Abase = Ag + mat + (size_t)(bm * 128) * SDIM;
    const float* Bbase = Bg + mat + bn * 128;

    float c[4][4][4];
    #pragma unroll
    for (int i = 0; i < 4; i++)
        #pragma unroll
        for (int j = 0; j < 4; j++)
            #pragma unroll
            for (int r = 0; r < 4; r++) c[i][j][r] = 0.f;

    for (int kt = 0; kt < SDIM; kt += KT) {
        // Load A tile 128x32 (convert to tf32, store k-major for fragment reads)
        #pragma unroll
        for (int i = 0; i < 4; i++) {
            int idx = tid + i * 256;
            int row = idx >> 3;           // 0..127
            int kq  = (idx & 7) << 2;     // 0..28 step 4
            float4 v = *reinterpret_cast<const float4*>(
                Abase + (size_t)row * SDIM + kt + kq);
            As[kq + 0][row] = f2tf(v.x);
            As[kq + 1][row] = f2tf(v.y);
            As[kq + 2][row] = f2tf(v.z);
            As[kq + 3][row] = f2tf(v.w);
        }
        // Load B tile 32x128
        #pragma unroll
        for (int i = 0; i < 4; i++) {
            int idx  = tid + i * 256;
            int krow = idx >> 5;          // 0..31
            int nq   = (idx & 31) << 2;   // 0..124 step 4
            float4 v = *reinterpret_cast<const float4*>(
                Bbase + (size_t)(kt + krow) * SDIM + nq);
            uint4 u;
            u.x = f2tf(v.x); u.y = f2tf(v.y); u.z = f2tf(v.z); u.w = f2tf(v.w);
            *reinterpret_cast<uint4*>(&Bs[krow][nq]) = u;
        }
        __syncthreads();

        #pragma unroll
        for (int kk = 0; kk < KT; kk += 8) {
            uint32_t af[4][4], bf[4][2];
            #pragma unroll
            for (int ti = 0; ti < 4; ti++) {
                int m = wm * 64 + ti * 16 + lr;
                af[ti][0] = As[kk + lc][m];
                af[ti][1] = As[kk + lc][m + 8];
                af[ti][2] = As[kk + lc + 4][m];
                af[ti][3] = As[kk + lc + 4][m + 8];
            }
            #pragma unroll
            for (int tj = 0; tj < 4; tj++) {
                int n = wn * 32 + tj * 8 + lr;
                bf[tj][0] = Bs[kk + lc][n];
                bf[tj][1] = Bs[kk + lc + 4][n];
            }
            #pragma unroll
            for (int ti = 0; ti < 4; ti++)
                #pragma unroll
                for (int tj = 0; tj < 4; tj++)
                    mma_tf32(c[ti][tj], af[ti], bf[tj]);
        }
        __syncthreads();
    }

    const float scale = 0.03125f;  // 1/sqrt(1024)
    #pragma unroll
    for (int ti = 0; ti < 4; ti++) {
        #pragma unroll
        for (int tj = 0; tj < 4; tj++) {
            int i0 = bm * 128 + wm * 64 + ti * 16 + lr;
            int j0 = bn * 128 + wn * 32 + tj * 8 + lc * 2;
            #pragma unroll
            for (int h = 0; h < 2; h++) {
                int i = i0 + h * 8;
                float v0 = c[ti][tj][h * 2 + 0];
                float v1 = c[ti][tj][h * 2 + 1];
                size_t off = mat + (size_t)i * SDIM + j0;
                if (fuse_epi) {
                    float2 bb = *reinterpret_cast<const float2*>(AddM + off);
                    float2 mm = *reinterpret_cast<const float2*>(
                        Mask + (size_t)i * SDIM + j0);
                    v0 = (v0 + bb.x) * scale + mm.x;
                    v1 = (v1 + bb.y) * scale + mm.y;
                }
                float2 o; o.x = v0; o.y = v1;
                *reinterpret_cast<float2*>(Out + off) = o;
            }
        }
    }
}

// One CTA (256 threads) per row of 1024; in-place softmax on g_attn.
__global__ __launch_bounds__(256) void softmax_kernel() {
    const size_t row = blockIdx.x;
    float* p = g_attn + row * SDIM;
    const int tid = threadIdx.x;
    const int warp = tid >> 5, lane = tid & 31;
    __shared__ float sred[8];

    float4 v = reinterpret_cast<float4*>(p)[tid];

    // row max
    float m = fmaxf(fmaxf(v.x, v.y), fmaxf(v.z, v.w));
    #pragma unroll
    for (int o = 16; o; o >>= 1) m = fmaxf(m, __shfl_xor_sync(0xffffffffu, m, o));
    if (lane == 0) sred[warp] = m;
    __syncthreads();
    m = sred[0];
    #pragma unroll
    for (int i = 1; i < 8; i++) m = fmaxf(m, sred[i]);
    __syncthreads();

    // exp + row sum
    v.x = expf(v.x - m);
    v.y = expf(v.y - m);
    v.z = expf(v.z - m);
    v.w = expf(v.w - m);
    float s = v.x + v.y + v.z + v.w;
    #pragma unroll
    for (int o = 16; o; o >>= 1) s += __shfl_xor_sync(0xffffffffu, s, o);
    if (lane == 0) sred[warp] = s;
    __syncthreads();
    s = sred[0];
    #pragma unroll
    for (int i = 1; i < 8; i++) s += sred[i];

    float inv = 1.0f / s;
    v.x *= inv; v.y *= inv; v.z *= inv; v.w *= inv;
    reinterpret_cast<float4*>(p)[tid] = v;
}

extern "C" void kernel_launch(void* const* d_in, const int* in_sizes, int n_in,
                              void* d_out, int out_size) {
    const float* A    = (const float*)d_in[0];
    const float* J    = (const float*)d_in[1];
    const float* B    = (const float*)d_in[2];
    const float* P    = (const float*)d_in[3];
    const float* mask = (const float*)d_in[4];
    float* out = (float*)d_out;

    float* attn = nullptr;
    cudaGetSymbolAddress((void**)&attn, g_attn);

    dim3 grid(SDIM / 128, SDIM / 128, BHN);  // 8 x 8 x 64
    gemm_kernel<<<grid, 256>>>(A, J, B, mask, attn, 1);
    softmax_kernel<<<BHN * SDIM, 256>>>();
    gemm_kernel<<<grid, 256>>>(attn, P, nullptr, nullptr, out, 0);
}

// round 4
// speedup vs baseline: 1.9261x; 1.9261x over previous
#include <cuda_runtime.h>
#include <cstdint>

#define SDIM 1024
#define BHN  64

// 256 MB scratch for logits / attention weights (device global: allocation-free).
__device__ __align__(16) float g_attn[(size_t)BHN * SDIM * SDIM];

__device__ __forceinline__ uint32_t f2tf(float x) {
    uint32_t r;
    asm("cvt.rna.tf32.f32 %0, %1;" : "=r"(r) : "f"(x));
    return r;
}

__device__ __forceinline__ uint32_t smem_u32(const void* p) {
    uint32_t a;
    asm("{ .reg .u64 t; cvta.to.shared.u64 t, %1; cvt.u32.u64 %0, t; }"
        : "=r"(a) : "l"(p));
    return a;
}

__device__ __forceinline__ void ldsm4(uint32_t a[4], uint32_t addr) {
    asm volatile("ldmatrix.sync.aligned.m8n8.x4.shared.b16 {%0,%1,%2,%3}, [%4];"
        : "=r"(a[0]), "=r"(a[1]), "=r"(a[2]), "=r"(a[3]) : "r"(addr));
}

__device__ __forceinline__ void mma_tf32(float c[4], const uint32_t a[4],
                                         uint32_t b0, uint32_t b1) {
    asm volatile(
        "mma.sync.aligned.m16n8k8.row.col.f32.tf32.tf32.f32 "
        "{%0,%1,%2,%3}, {%4,%5,%6,%7}, {%8,%9}, {%0,%1,%2,%3};"
        : "+f"(c[0]), "+f"(c[1]), "+f"(c[2]), "+f"(c[3])
        : "r"(a[0]), "r"(a[1]), "r"(a[2]), "r"(a[3]), "r"(b0), "r"(b1));
}

// CTA tile 128x128, 4 warps (2x2), warp tile 64x64, mma m16n8k8 tf32.
// A in smem: row-major [m][32 tf32] with 16B-chunk XOR swizzle (ldmatrix reads).
// B in smem: fragment-packed [kg][ntile][lane^swz][slot] (LDS.64 reads).
// fuse_epi=1: out = (acc + AddM) * scale + Mask   (QK pass -> g_attn)
// fuse_epi=0: out = acc                           (attn @ P -> d_out)
__global__ __launch_bounds__(128) void gemm_kernel(
    const float* __restrict__ Ag, const float* __restrict__ Bg,
    const float* __restrict__ AddM, const float* __restrict__ Mask,
    float* __restrict__ Out, int fuse_epi)
{
    __shared__ uint32_t Asm[128 * 32];       // 16 KB
    __shared__ uint32_t Bsm[4 * 16 * 64];    // 16 KB

    const int bm = blockIdx.x, bn = blockIdx.y, bh = blockIdx.z;
    const int tid  = threadIdx.x;
    const int warp = tid >> 5, lane = tid & 31;
    const int wm = warp >> 1, wn = warp & 1;   // 2 x 2 warp grid
    const int lr = lane >> 2, lc = lane & 3;

    const size_t mat = (size_t)bh * SDIM * SDIM;
    const float* Abase = Ag + mat + (size_t)(bm * 128) * SDIM;
    const float* Bbase = Bg + mat + bn * 128;

    float c[4][8][4];
    #pragma unroll
    for (int i = 0; i < 4; i++)
        #pragma unroll
        for (int j = 0; j < 8; j++)
            #pragma unroll
            for (int r = 0; r < 4; r++) c[i][j][r] = 0.f;

    // ldmatrix lane geometry: lanes 0-7 -> rows m+0..7 (chunk k/4),
    // 8-15 -> m+8..15 (chunk), 16-23 -> m+0..7 (chunk+1), 24-31 -> m+8..15 (chunk+1)
    const int moff = ((lane >> 3) & 1) * 8 + (lane & 7);
    const int csel = lane >> 4;
    const uint32_t As_addr = smem_u32(Asm);

    for (int kt = 0; kt < SDIM; kt += 32) {
        // ---- fill A tile 128x32: LDG.128 -> cvt tf32 -> STS.128 (swizzled) ----
        #pragma unroll
        for (int i = 0; i < 8; i++) {
            int idx = tid + i * 128;
            int m   = idx >> 3;
            int ch  = idx & 7;                 // 16B chunk within the 128B row
            float4 v = *reinterpret_cast<const float4*>(
                Abase + (size_t)m * SDIM + kt + ch * 4);
            uint4 u;
            u.x = f2tf(v.x); u.y = f2tf(v.y); u.z = f2tf(v.z); u.w = f2tf(v.w);
            int pc = ch ^ (m & 7);
            *reinterpret_cast<uint4*>(&Asm[m * 32 + pc * 4]) = u;
        }
        // ---- fill B tile 32x128: fragment-packed scatter ----
        #pragma unroll
        for (int i = 0; i < 8; i++) {
            int idx = tid + i * 128;
            int kr  = idx >> 5;
            int nq  = (idx & 31) << 2;
            float4 v = *reinterpret_cast<const float4*>(
                Bbase + (size_t)(kt + kr) * SDIM + nq);
            int kg = kr >> 3, kq = kr & 7;
            int slot = kq >> 2, kqc = kq & 3;
            uint32_t* bb = &Bsm[kg * 1024];
            float vv[4] = {v.x, v.y, v.z, v.w};
            #pragma unroll
            for (int e = 0; e < 4; e++) {
                int n  = nq + e;
                int nt = n >> 3;
                int lo = ((n & 7) << 2) + kqc;       // owner lane in the mma
                int pl = lo ^ (nt & 15);             // bank-spread swizzle
                bb[nt * 64 + pl * 2 + slot] = f2tf(vv[e]);
            }
        }
        __syncthreads();

        #pragma unroll
        for (int kk = 0; kk < 32; kk += 8) {
            int kg = kk >> 3;
            uint32_t af[4][4];
            #pragma unroll
            for (int ti = 0; ti < 4; ti++) {
                int m     = wm * 64 + ti * 16 + moff;
                int chunk = (kk >> 2) + csel;
                uint32_t addr = As_addr +
                    ((uint32_t)(m * 32 + ((chunk ^ (m & 7)) << 2)) << 2);
                ldsm4(af[ti], addr);
            }
            #pragma unroll
            for (int tj = 0; tj < 8; tj++) {
                int nt = wn * 8 + tj;
                int pl = lane ^ (nt & 15);
                uint2 b = *reinterpret_cast<const uint2*>(
                    &Bsm[kg * 1024 + nt * 64 + pl * 2]);
                #pragma unroll
                for (int ti = 0; ti < 4; ti++)
                    mma_tf32(c[ti][tj], af[ti], b.x, b.y);
            }
        }
        __syncthreads();
    }

    // ---- epilogue ----
    const float scale = 0.03125f;  // 1/sqrt(1024)
    #pragma unroll
    for (int ti = 0; ti < 4; ti++) {
        #pragma unroll
        for (int tj = 0; tj < 8; tj++) {
            int i0 = bm * 128 + wm * 64 + ti * 16 + lr;
            int j0 = bn * 128 + wn * 64 + tj * 8 + lc * 2;
            #pragma unroll
            for (int h = 0; h < 2; h++) {
                int i = i0 + h * 8;
                float v0 = c[ti][tj][h * 2 + 0];
                float v1 = c[ti][tj][h * 2 + 1];
                size_t off = mat + (size_t)i * SDIM + j0;
                if (fuse_epi) {
                    float2 bb = *reinterpret_cast<const float2*>(AddM + off);
                    float2 mm = *reinterpret_cast<const float2*>(
                        Mask + (size_t)i * SDIM + j0);
                    v0 = (v0 + bb.x) * scale + mm.x;
                    v1 = (v1 + bb.y) * scale + mm.y;
                }
                float2 o; o.x = v0; o.y = v1;
                *reinterpret_cast<float2*>(Out + off) = o;
            }
        }
    }
}

// One CTA (256 threads) per row of 1024; in-place softmax on g_attn.
__global__ __launch_bounds__(256) void softmax_kernel() {
    const size_t row = blockIdx.x;
    float* p = g_attn + row * SDIM;
    const int tid = threadIdx.x;
    const int warp = tid >> 5, lane = tid & 31;
    __shared__ float sred[8];

    float4 v = reinterpret_cast<float4*>(p)[tid];

    float m = fmaxf(fmaxf(v.x, v.y), fmaxf(v.z, v.w));
    #pragma unroll
    for (int o = 16; o; o >>= 1) m = fmaxf(m, __shfl_xor_sync(0xffffffffu, m, o));
    if (lane == 0) sred[warp] = m;
    __syncthreads();
    m = sred[0];
    #pragma unroll
    for (int i = 1; i < 8; i++) m = fmaxf(m, sred[i]);
    __syncthreads();

    v.x = expf(v.x - m);
    v.y = expf(v.y - m);
    v.z = expf(v.z - m);
    v.w = expf(v.w - m);
    float s = v.x + v.y + v.z + v.w;
    #pragma unroll
    for (int o = 16; o; o >>= 1) s += __shfl_xor_sync(0xffffffffu, s, o);
    if (lane == 0) sred[warp] = s;
    __syncthreads();
    s = sred[0];
    #pragma unroll
    for (int i = 1; i < 8; i++) s += sred[i];

    float inv = 1.0f / s;
    v.x *= inv; v.y *= inv; v.z *= inv; v.w *= inv;
    reinterpret_cast<float4*>(p)[tid] = v;
}

extern "C" void kernel_launch(void* const* d_in, const int* in_sizes, int n_in,
                              void* d_out, int out_size) {
    const float* A    = (const float*)d_in[0];
    const float* J    = (const float*)d_in[1];
    const float* B    = (const float*)d_in[2];
    const float* P    = (const float*)d_in[3];
    const float* mask = (const float*)d_in[4];
    float* out = (float*)d_out;

    float* attn = nullptr;
    cudaGetSymbolAddress((void**)&attn, g_attn);

    dim3 grid(SDIM / 128, SDIM / 128, BHN);  // 8 x 8 x 64
    gemm_kernel<<<grid, 128>>>(A, J, B, mask, attn, 1);
    softmax_kernel<<<BHN * SDIM, 256>>>();
    gemm_kernel<<<grid, 128>>>(attn, P, nullptr, nullptr, out, 0);
}